// round 2
// baseline (speedup 1.0000x reference)
#include <cuda_runtime.h>
#include <cstdint>

// LSTM (B=16384, T=28, I=28, H=64) + linear classifier to 10 classes.
// One CTA = 128 batch elements, 512 threads. Per timestep:
//   G[128,256] = [x_t | h] (128x92)  @  [W_ih | W_hh]^T (92x256)  + (b_ih+b_hh)
// computed as an fp32x2 packed-FMA register-tiled GEMM, followed by a fully
// register-local LSTM pointwise epilogue (c lives in registers, h in SMEM).

#define BDIM    16384
#define TSTEPS  28
#define IDIM    28
#define HDIM    64
#define G4      256          // 4*H
#define KTOT    92           // IDIM + HDIM
#define BT      128          // batch tile per CTA
#define NTHR    512
#define AS_STR  130          // A_s row stride (pad 2: keeps 8B align for f32x2 loads)

// ---- f32x2 helpers (sm_100+) --------------------------------------------
__device__ __forceinline__ unsigned long long ffma2(unsigned long long a,
                                                    unsigned long long b,
                                                    unsigned long long c) {
    unsigned long long d;
    asm("fma.rn.f32x2 %0, %1, %2, %3;" : "=l"(d) : "l"(a), "l"(b), "l"(c));
    return d;
}
__device__ __forceinline__ unsigned long long pk2(float a) {  // {a,a}
    unsigned long long d;
    asm("mov.b64 %0, {%1, %2};" : "=l"(d) : "f"(a), "f"(a));
    return d;
}
__device__ __forceinline__ unsigned long long pkp(float lo, float hi) {
    unsigned long long d;
    asm("mov.b64 %0, {%1, %2};" : "=l"(d) : "f"(lo), "f"(hi));
    return d;
}
__device__ __forceinline__ float2 unpk(unsigned long long v) {
    float2 r;
    asm("mov.b64 {%0, %1}, %2;" : "=f"(r.x), "=f"(r.y) : "l"(v));
    return r;
}

// ---- activations (EX2/RCP based; accurate to ~1e-7 rel, safe at +-inf) ---
__device__ __forceinline__ float sigf(float v) {
    return __fdividef(1.0f, 1.0f + __expf(-v));
}
__device__ __forceinline__ float tnhf(float v) {
    return 1.0f - 2.0f * __fdividef(1.0f, 1.0f + __expf(2.0f * v));
}

__global__ void __launch_bounds__(NTHR, 1)
lstm_cls_kernel(const float* __restrict__ x,
                const float* __restrict__ Wih,   // [256,28]
                const float* __restrict__ Whh,   // [256,64]
                const float* __restrict__ bih,   // [256]
                const float* __restrict__ bhh,   // [256]
                const float* __restrict__ Wcls,  // [10,64]
                const float* __restrict__ bcls,  // [10]
                float* __restrict__ out)         // [B,10]
{
    extern __shared__ float sm[];
    float* As   = sm;                         // [KTOT][AS_STR]  rows 0..27 = x_t, 28..91 = h
    float* Wt   = sm + KTOT * AS_STR;         // [KTOT][256]  transposed weights
    float* bias = Wt + KTOT * G4;             // [256]

    const int tid = threadIdx.x;
    const int bi  = tid >> 5;                 // 0..15 : batch group (8 batches)
    const int ri  = tid & 31;                 // 0..31 : row group  (8 rows, stride 32)
    const int bbase = blockIdx.x * BT;
    const int bcol  = bi << 3;                // first of this thread's 8 batch columns

    // --- one-time: weights transposed into SMEM, fused bias -------------
    for (int idx = tid; idx < KTOT * G4; idx += NTHR) {
        int k = idx >> 8;            // /256
        int r = idx & 255;
        float w = (k < IDIM) ? Wih[r * IDIM + k] : Whh[r * HDIM + (k - IDIM)];
        Wt[k * G4 + r] = w;
    }
    for (int r = tid; r < G4; r += NTHR) bias[r] = bih[r] + bhh[r];
    // zero h rows (rows 28..91)
    for (int idx = tid; idx < HDIM * AS_STR; idx += NTHR)
        As[IDIM * AS_STR + idx] = 0.0f;

    // --- prefetch x_0 into registers ------------------------------------
    const float* __restrict__ xb = x + (size_t)bbase * TSTEPS * IDIM;
    float xr[7];
#pragma unroll
    for (int i = 0; i < 7; i++) {
        int idx = tid + i * NTHR;            // 0..3583 = 128*28 exactly
        int b = idx / IDIM, k = idx % IDIM;
        xr[i] = xb[b * (TSTEPS * IDIM) + k]; // t = 0
    }

    float cst[4][2][2] = {};                  // c state: [pair u][jj][half]
    unsigned long long acc[4][8];

    for (int t = 0; t < TSTEPS; ++t) {
        // write x_t rows (prev GEMM readers finished before last sync)
#pragma unroll
        for (int i = 0; i < 7; i++) {
            int idx = tid + i * NTHR;
            int b = idx / IDIM, k = idx % IDIM;
            As[k * AS_STR + b] = xr[i];
        }
        // prefetch x_{t+1} (global latency overlaps the sync + GEMM)
        if (t < TSTEPS - 1) {
#pragma unroll
            for (int i = 0; i < 7; i++) {
                int idx = tid + i * NTHR;
                int b = idx / IDIM, k = idx % IDIM;
                xr[i] = xb[b * (TSTEPS * IDIM) + (t + 1) * IDIM + k];
            }
        }
        __syncthreads();                      // x + h writes visible

        // --- GEMM: acc[b,r] = bias[r] + sum_k A[k,b] * Wt[k,r] ----------
#pragma unroll
        for (int ur = 0; ur < 8; ur++) {
            unsigned long long bv = pk2(bias[ri + 32 * ur]);
            acc[0][ur] = bv; acc[1][ur] = bv; acc[2][ur] = bv; acc[3][ur] = bv;
        }
#pragma unroll 2
        for (int k = 0; k < KTOT; k++) {
            const float* __restrict__ arow = As + k * AS_STR + bcol;
            unsigned long long h0 = *reinterpret_cast<const unsigned long long*>(arow + 0);
            unsigned long long h1 = *reinterpret_cast<const unsigned long long*>(arow + 2);
            unsigned long long h2 = *reinterpret_cast<const unsigned long long*>(arow + 4);
            unsigned long long h3 = *reinterpret_cast<const unsigned long long*>(arow + 6);
            const float* __restrict__ wrow = Wt + (k << 8) + ri;
#pragma unroll
            for (int ur = 0; ur < 8; ur++) {
                unsigned long long wd = pk2(wrow[ur * 32]);
                acc[0][ur] = ffma2(h0, wd, acc[0][ur]);
                acc[1][ur] = ffma2(h1, wd, acc[1][ur]);
                acc[2][ur] = ffma2(h2, wd, acc[2][ur]);
                acc[3][ur] = ffma2(h3, wd, acc[3][ur]);
            }
        }

        // --- LSTM pointwise epilogue (fully register-local) -------------
        // r = ri + 32*ur  ->  gate = ur>>1, j = ri + 32*(ur&1)
        float hv[4][2][2];
#pragma unroll
        for (int u = 0; u < 4; u++) {
#pragma unroll
            for (int jj = 0; jj < 2; jj++) {
                float2 gi = unpk(acc[u][0 + jj]);   // input gate preact
                float2 gf = unpk(acc[u][2 + jj]);   // forget gate
                float2 gg = unpk(acc[u][4 + jj]);   // cell gate
                float2 go = unpk(acc[u][6 + jj]);   // output gate
#pragma unroll
                for (int hx = 0; hx < 2; hx++) {
                    float iv = sigf(hx ? gi.y : gi.x);
                    float fv = sigf(hx ? gf.y : gf.x);
                    float gv = tnhf(hx ? gg.y : gg.x);
                    float ov = sigf(hx ? go.y : go.x);
                    float c  = fv * cst[u][jj][hx] + iv * gv;
                    cst[u][jj][hx] = c;
                    hv[u][jj][hx]  = ov * tnhf(c);
                }
            }
        }
        __syncthreads();                      // all GEMM reads of old h done

        // write new h: rows 28 + j, columns bcol + 2u (+half), 8B stores
#pragma unroll
        for (int u = 0; u < 4; u++) {
#pragma unroll
            for (int jj = 0; jj < 2; jj++) {
                int row = IDIM + ri + 32 * jj;
                *reinterpret_cast<unsigned long long*>(
                    &As[row * AS_STR + bcol + 2 * u]) =
                    pkp(hv[u][jj][0], hv[u][jj][1]);
            }
        }
    }
    __syncthreads();

    // --- classifier: out[b,cls] = b_cls[cls] + sum_j h[b,j]*Wcls[cls,j] --
    for (int idx = tid; idx < BT * 10; idx += NTHR) {
        int b = idx / 10, cls = idx % 10;
        float s = bcls[cls];
        const float* __restrict__ wc = Wcls + cls * HDIM;
#pragma unroll
        for (int j = 0; j < HDIM; j++)
            s += As[(IDIM + j) * AS_STR + b] * __ldg(&wc[j]);
        out[(size_t)(bbase + b) * 10 + cls] = s;
    }
}

extern "C" void kernel_launch(void* const* d_in, const int* in_sizes, int n_in,
                              void* d_out, int out_size) {
    const float* x    = (const float*)d_in[0];
    const float* Wih  = (const float*)d_in[1];
    const float* Whh  = (const float*)d_in[2];
    const float* bih  = (const float*)d_in[3];
    const float* bhh  = (const float*)d_in[4];
    const float* Wcls = (const float*)d_in[5];
    const float* bcls = (const float*)d_in[6];
    float* out = (float*)d_out;

    const int smem = (KTOT * AS_STR + KTOT * G4 + G4) * (int)sizeof(float); // ~143 KB
    cudaFuncSetAttribute(lstm_cls_kernel,
                         cudaFuncAttributeMaxDynamicSharedMemorySize, smem);
    lstm_cls_kernel<<<BDIM / BT, NTHR, smem>>>(x, Wih, Whh, bih, bhh, Wcls, bcls, out);
}

// round 6
// speedup vs baseline: 1.6352x; 1.6352x over previous
#include <cuda_runtime.h>
#include <cuda_bf16.h>
#include <cstdint>

// LSTM (B=16384, T=28, I=28, H=64) + classifier via warp-level mma.sync bf16
// (plain sm_100 target: no tcgen05 available in this build pipeline).
// One CTA = 128 batches. Per timestep: D[128,256] = A[128,96] * B[256,96]^T,
// A=[x_t|pad|h], B = gate-interleaved weights (row n=4j+g), fp32 accuracy via
// bf16 split: D = Ah*Bh + Ah*Bl + Al*Bh (rel err ~2^-16).
// Gate interleaving puts all 4 gates of a hidden unit in one n8 tile ->
// a single shfl.xor(1) exchange gives each thread a full LSTM unit; c stays
// in registers, D never touches SMEM.

#define NTHR    512
#define BT      128
#define TSTEPS  28
#define IDIM    28
#define HDIM    64

// SMEM layout (bytes). A panels: 128 rows x 64 bf16 cols (128B rows, SW128).
// B panels: 256 rows x 64 bf16 cols.
#define OFF_BIAS  0
#define OFF_AHI0  1024
#define OFF_AHI1  (OFF_AHI0 + 16384)
#define OFF_ALO0  (OFF_AHI1 + 16384)
#define OFF_ALO1  (OFF_ALO0 + 16384)
#define OFF_BHI0  (OFF_ALO1 + 16384)     // 66560
#define OFF_BHI1  (OFF_BHI0 + 32768)
#define OFF_BLO0  (OFF_BHI1 + 32768)
#define OFF_BLO1  (OFF_BLO0 + 32768)
#define SMEM_SZ   (OFF_BLO1 + 32768)     // 197632 (~193KB)

#define SWZ(b) ((b) ^ (((b) >> 3) & 0x70))

static __device__ __forceinline__ uint32_t smem_u32(const void* p) {
    uint32_t a;
    asm("{ .reg .u64 t; cvta.to.shared.u64 t, %1; cvt.u32.u64 %0, t; }" : "=r"(a) : "l"(p));
    return a;
}
#define LDSM4(R0, R1, R2, R3, A)                                             \
    asm volatile("ldmatrix.sync.aligned.m8n8.x4.shared.b16 {%0,%1,%2,%3}, [%4];" \
                 : "=r"(R0), "=r"(R1), "=r"(R2), "=r"(R3) : "r"(A))
#define MMA16816(D, A, B0, B1)                                               \
    asm volatile("mma.sync.aligned.m16n8k16.row.col.f32.bf16.bf16.f32 "      \
                 "{%0,%1,%2,%3}, {%4,%5,%6,%7}, {%8,%9}, {%0,%1,%2,%3};"     \
                 : "+f"((D)[0]), "+f"((D)[1]), "+f"((D)[2]), "+f"((D)[3])    \
                 : "r"((A)[0]), "r"((A)[1]), "r"((A)[2]), "r"((A)[3]),       \
                   "r"(B0), "r"(B1))

static __device__ __forceinline__ float sigf(float v) {
    return __fdividef(1.0f, 1.0f + __expf(-v));
}
static __device__ __forceinline__ float tnhf(float v) {
    return 1.0f - 2.0f * __fdividef(1.0f, 1.0f + __expf(2.0f * v));
}
// bf16 split: v ~= hi + lo, each bf16 (combined rel err ~2^-16)
static __device__ __forceinline__ void bsplit(float v, uint16_t& hi, uint16_t& lo) {
    __nv_bfloat16 h = __float2bfloat16_rn(v);
    __nv_bfloat16 l = __float2bfloat16_rn(v - __bfloat162float(h));
    hi = __bfloat16_as_ushort(h);
    lo = __bfloat16_as_ushort(l);
}

__global__ void __launch_bounds__(NTHR, 1)
lstm_mma_kernel(const float* __restrict__ x,
                const float* __restrict__ Wih,   // [256,28]
                const float* __restrict__ Whh,   // [256,64]
                const float* __restrict__ bih,
                const float* __restrict__ bhh,
                const float* __restrict__ Wcls,  // [10,64]
                const float* __restrict__ bcls,  // [10]
                float* __restrict__ out)         // [B,10]
{
    extern __shared__ char smem[];
    const uint32_t sb = smem_u32(smem);
    const int tid  = threadIdx.x;
    const int wid  = tid >> 5;
    const int lane = tid & 31;
    const int mw   = wid >> 1;           // M chunk (16 rows)
    const int nh   = wid & 1;            // N half (128 gate-rows)
    float* biasS = (float*)(smem + OFF_BIAS);

    // ---- bias, gate-interleaved: biasS[4j+g] = bih[g*64+j]+bhh[...] -----
    for (int n = tid; n < 256; n += NTHR) {
        int j = n >> 2, g = n & 3;
        biasS[n] = bih[g * HDIM + j] + bhh[g * HDIM + j];
    }
    // ---- zero all A panels (covers pads + initial h = 0) ----------------
    for (int i = tid; i < 4 * 16384 / 16; i += NTHR)
        ((uint4*)(smem + OFF_AHI0))[i] = make_uint4(0, 0, 0, 0);

    // ---- B fill: row n'=4j+g, k: 0..27=Wih, 28..31=0, 32..95=Whh -------
    //      panel0 = k 0..63, panel1 = k 64..95 (cols 0..31)
    for (int idx = tid; idx < 256 * 96; idx += NTHR) {
        int n = idx / 96, k = idx % 96;
        int j = n >> 2, g = n & 3, orow = g * HDIM + j;
        float w = 0.0f;
        if (k < IDIM)      w = Wih[orow * IDIM + k];
        else if (k >= 32)  w = Whh[orow * HDIM + (k - 32)];
        int p  = k >> 6, kl = k & 63;
        uint32_t sw = SWZ((uint32_t)(n * 128 + kl * 2));
        uint16_t hb, lb; bsplit(w, hb, lb);
        *(uint16_t*)(smem + (p ? OFF_BHI1 : OFF_BHI0) + sw) = hb;
        *(uint16_t*)(smem + (p ? OFF_BLO1 : OFF_BLO0) + sw) = lb;
    }

    // ---- prefetch x_0 ---------------------------------------------------
    const float* __restrict__ xb = x + (size_t)blockIdx.x * BT * TSTEPS * IDIM;
    float xr[7];
#pragma unroll
    for (int i = 0; i < 7; i++) {
        int idx = tid + i * NTHR;               // 3584 = 128*28 exactly
        int b = idx / IDIM, k = idx % IDIM;
        xr[i] = xb[b * (TSTEPS * IDIM) + k];
    }

    // ---- per-thread constants ------------------------------------------
    // ldmatrix A: lanes 0-15 rows, lanes 16-31 second 16B chunk
    const int arow   = mw * 16 + (lane & 15);
    const int achunk = (lane >> 4) * 16;
    // ldmatrix B (2 n8-tiles per x4)
    const int brow_l = ((lane >> 4) << 3) + (lane & 7);
    const int bchunk = ((lane >> 3) & 1) * 16;
    // epilogue unit: b = batch row, jpar = which j within tile
    const int jpar = (lane & 3) >> 1;
    const int bown = mw * 16 + (lane >> 2) + ((lane & 1) << 3);
    const int jbase = 32 * nh;
    const uint32_t apan_hi_h = sb + (nh ? OFF_AHI1 : OFF_AHI0);  // h dest
    const uint32_t apan_lo_h = sb + (nh ? OFF_ALO1 : OFF_ALO0);

    float cs[16];
#pragma unroll
    for (int m = 0; m < 16; m++) cs[m] = 0.0f;

    float* hst = (float*)(smem + OFF_BHI0);      // classifier staging (reuse B)

    for (int t = 0; t < TSTEPS; ++t) {
        // ---- write x_t into A panel0 cols 0..27 (bf16 hi/lo) ------------
#pragma unroll
        for (int i = 0; i < 7; i++) {
            int idx = tid + i * NTHR;
            int b = idx / IDIM, k = idx % IDIM;
            uint32_t sw = SWZ((uint32_t)(b * 128 + k * 2));
            uint16_t hb, lb; bsplit(xr[i], hb, lb);
            *(uint16_t*)(smem + OFF_AHI0 + sw) = hb;
            *(uint16_t*)(smem + OFF_ALO0 + sw) = lb;
        }
        __syncthreads();     // x_t + h (written end of prev iter) visible

        // ---- GEMM: 6 k16 steps x 8 tile-pairs x 3 split products --------
        float d[16][4];
#pragma unroll
        for (int m = 0; m < 16; m++) {
            d[m][0] = 0.0f; d[m][1] = 0.0f; d[m][2] = 0.0f; d[m][3] = 0.0f;
        }
#pragma unroll
        for (int ks = 0; ks < 6; ks++) {
            const int p  = (ks < 4) ? 0 : 1;
            const int cb = (ks < 4) ? ks * 32 : (ks - 4) * 32;
            const uint32_t aswz = SWZ((uint32_t)(arow * 128 + cb + achunk));
            uint32_t ah[4], al[4];
            LDSM4(ah[0], ah[1], ah[2], ah[3],
                  sb + (p ? OFF_AHI1 : OFF_AHI0) + aswz);
            LDSM4(al[0], al[1], al[2], al[3],
                  sb + (p ? OFF_ALO1 : OFF_ALO0) + aswz);
#pragma unroll
            for (int g2 = 0; g2 < 8; g2++) {
                const int nb = nh * 128 + g2 * 16;
                const uint32_t bswz =
                    SWZ((uint32_t)((nb + brow_l) * 128 + cb + bchunk));
                uint32_t bhv[4], blv[4];
                LDSM4(bhv[0], bhv[1], bhv[2], bhv[3],
                      sb + (p ? OFF_BHI1 : OFF_BHI0) + bswz);
                LDSM4(blv[0], blv[1], blv[2], blv[3],
                      sb + (p ? OFF_BLO1 : OFF_BLO0) + bswz);
                MMA16816(d[2 * g2],     ah, bhv[0], bhv[1]);
                MMA16816(d[2 * g2],     ah, blv[0], blv[1]);
                MMA16816(d[2 * g2],     al, bhv[0], bhv[1]);
                MMA16816(d[2 * g2 + 1], ah, bhv[2], bhv[3]);
                MMA16816(d[2 * g2 + 1], ah, blv[2], blv[3]);
                MMA16816(d[2 * g2 + 1], al, bhv[2], bhv[3]);
            }
        }
        __syncthreads();     // all A reads done before h overwrite

        // ---- prefetch x_{t+1} (overlaps epilogue) -----------------------
        if (t < TSTEPS - 1) {
#pragma unroll
            for (int i = 0; i < 7; i++) {
                int idx = tid + i * NTHR;
                int b = idx / IDIM, k = idx % IDIM;
                xr[i] = xb[b * (TSTEPS * IDIM) + (t + 1) * IDIM + k];
            }
        }

        // ---- epilogue: per n8-tile, shfl-exchange -> full LSTM unit -----
#pragma unroll
        for (int nt = 0; nt < 16; nt++) {
            float c0 = d[nt][0], c1 = d[nt][1], c2 = d[nt][2], c3 = d[nt][3];
            float s0 = (lane & 1) ? c0 : c2;
            float s1 = (lane & 1) ? c1 : c3;
            float r0 = __shfl_xor_sync(0xFFFFFFFFu, s0, 1);
            float r1 = __shfl_xor_sync(0xFFFFFFFFu, s1, 1);
            float gi, gf, gg, go;
            if (lane & 1) { gi = r0; gf = r1; gg = c2; go = c3; }
            else          { gi = c0; gf = c1; gg = r0; go = r1; }
            const int j = jbase + 2 * nt + jpar;
            float4 bb = *(const float4*)(biasS + 4 * j);
            float iv = sigf(gi + bb.x);
            float fv = sigf(gf + bb.y);
            float gv = tnhf(gg + bb.z);
            float ov = sigf(go + bb.w);
            float c  = fv * cs[nt] + iv * gv;
            cs[nt] = c;
            float h = ov * tnhf(c);
            // write h into A (panel by j range) for next step's GEMM
            const int colb = nh ? (4 * nt + 2 * jpar) : (64 + 4 * nt + 2 * jpar);
            const uint32_t sw = SWZ((uint32_t)(bown * 128 + colb));
            uint16_t hb, lb; bsplit(h, hb, lb);
            *(uint16_t*)((char*)smem + (apan_hi_h - sb) + sw) = hb;
            *(uint16_t*)((char*)smem + (apan_lo_h - sb) + sw) = lb;
            if (t == TSTEPS - 1) hst[bown * 65 + j] = h;   // stage for classifier
        }
    }
    __syncthreads();

    // ---- classifier: out[b,cls] = b_cls + sum_j h[b,j]*Wcls[cls,j] ------
    const int bbase = blockIdx.x * BT;
    for (int idx = tid; idx < BT * 10; idx += NTHR) {
        int b = idx / 10, cls = idx % 10;
        float s = bcls[cls];
        const float* __restrict__ wc = Wcls + cls * HDIM;
#pragma unroll
        for (int j = 0; j < HDIM; j++) s += hst[b * 65 + j] * __ldg(&wc[j]);
        out[(size_t)(bbase + b) * 10 + cls] = s;
    }
}

extern "C" void kernel_launch(void* const* d_in, const int* in_sizes, int n_in,
                              void* d_out, int out_size) {
    const float* x    = (const float*)d_in[0];
    const float* Wih  = (const float*)d_in[1];
    const float* Whh  = (const float*)d_in[2];
    const float* bih  = (const float*)d_in[3];
    const float* bhh  = (const float*)d_in[4];
    const float* Wcls = (const float*)d_in[5];
    const float* bcls = (const float*)d_in[6];
    float* out = (float*)d_out;

    cudaFuncSetAttribute(lstm_mma_kernel,
                         cudaFuncAttributeMaxDynamicSharedMemorySize, SMEM_SZ);
    lstm_mma_kernel<<<16384 / BT, NTHR, SMEM_SZ>>>(x, Wih, Whh, bih, bhh,
                                                   Wcls, bcls, out);
}

// round 8
// speedup vs baseline: 1.7434x; 1.0661x over previous
#include <cuda_runtime.h>
#include <cuda_bf16.h>
#include <cstdint>

// LSTM (B=16384, T=28, I=28, H=64) + classifier via warp-level mma.sync bf16.
// One CTA = 128 batches, 16 warps = 8 independent warp-PAIRS; pair mw owns
// batch rows [16mw,16mw+16). Per timestep: D[16,256] per pair = A*B^T,
// A=[x_t|pad|h] (pair rows), B = gate-interleaved weights (row n=4j+g).
// fp32 accuracy via bf16 split: D = Ah*Bh + Ah*Bl + Al*Bh (rel err ~2^-16).
// Pairs synchronize ONLY via named barriers (bar.sync mw+1, 64): no full-CTA
// sync in the recurrence -> pairs drift, MMA of one pair overlaps MUFU
// epilogue of another on the same SMSP.

#define NTHR    512
#define BT      128
#define TSTEPS  28
#define IDIM    28
#define HDIM    64

// SMEM layout (bytes). A panels: 128 rows x 64 bf16 cols (128B rows, SW128).
// B panels: 256 rows x 64 bf16 cols.
#define OFF_BIAS  0
#define OFF_AHI0  1024
#define OFF_AHI1  (OFF_AHI0 + 16384)
#define OFF_ALO0  (OFF_AHI1 + 16384)
#define OFF_ALO1  (OFF_ALO0 + 16384)
#define OFF_BHI0  (OFF_ALO1 + 16384)     // 66560
#define OFF_BHI1  (OFF_BHI0 + 32768)
#define OFF_BLO0  (OFF_BHI1 + 32768)
#define OFF_BLO1  (OFF_BLO0 + 32768)
#define OFF_HST   (OFF_BLO1 + 32768)     // 197632: 128 x 65 floats
#define SMEM_SZ   (OFF_HST + 128*65*4)   // 230912 (< 232448 cap)

#define SWZ(b) ((b) ^ (((b) >> 3) & 0x70))

static __device__ __forceinline__ uint32_t smem_u32(const void* p) {
    uint32_t a;
    asm("{ .reg .u64 t; cvta.to.shared.u64 t, %1; cvt.u32.u64 %0, t; }" : "=r"(a) : "l"(p));
    return a;
}
#define PAIR_BAR(ID)                                                         \
    asm volatile("bar.sync %0, 64;" :: "r"(ID) : "memory")
#define LDSM4(R0, R1, R2, R3, A)                                             \
    asm volatile("ldmatrix.sync.aligned.m8n8.x4.shared.b16 {%0,%1,%2,%3}, [%4];" \
                 : "=r"(R0), "=r"(R1), "=r"(R2), "=r"(R3) : "r"(A))
#define MMA16816(D, A, B0, B1)                                               \
    asm volatile("mma.sync.aligned.m16n8k16.row.col.f32.bf16.bf16.f32 "      \
                 "{%0,%1,%2,%3}, {%4,%5,%6,%7}, {%8,%9}, {%0,%1,%2,%3};"     \
                 : "+f"((D)[0]), "+f"((D)[1]), "+f"((D)[2]), "+f"((D)[3])    \
                 : "r"((A)[0]), "r"((A)[1]), "r"((A)[2]), "r"((A)[3]),       \
                   "r"(B0), "r"(B1))

static __device__ __forceinline__ float sigf(float v) {
    return __fdividef(1.0f, 1.0f + __expf(-v));
}
static __device__ __forceinline__ float tnhf(float v) {
    return 1.0f - 2.0f * __fdividef(1.0f, 1.0f + __expf(2.0f * v));
}
// bf16 split: v ~= hi + lo, each bf16 (combined rel err ~2^-16)
static __device__ __forceinline__ void bsplit(float v, uint16_t& hi, uint16_t& lo) {
    __nv_bfloat16 h = __float2bfloat16_rn(v);
    __nv_bfloat16 l = __float2bfloat16_rn(v - __bfloat162float(h));
    hi = __bfloat16_as_ushort(h);
    lo = __bfloat16_as_ushort(l);
}

__global__ void __launch_bounds__(NTHR, 1)
lstm_mma_kernel(const float* __restrict__ x,
                const float* __restrict__ Wih,   // [256,28]
                const float* __restrict__ Whh,   // [256,64]
                const float* __restrict__ bih,
                const float* __restrict__ bhh,
                const float* __restrict__ Wcls,  // [10,64]
                const float* __restrict__ bcls,  // [10]
                float* __restrict__ out)         // [B,10]
{
    extern __shared__ char smem[];
    const uint32_t sb = smem_u32(smem);
    const int tid  = threadIdx.x;
    const int wid  = tid >> 5;
    const int lane = tid & 31;
    const int mw   = wid >> 1;           // pair id: 16-row batch chunk
    const int nh   = wid & 1;            // N half (128 gate-rows)
    const int ptid = tid & 63;           // thread id within pair
    const int barid = mw + 1;            // named barrier (ids 1..8; 0 = CTA)
    float* biasS = (float*)(smem + OFF_BIAS);

    // ---- bias, gate-interleaved: biasS[4j+g] = bih[g*64+j]+bhh[...] -----
    for (int n = tid; n < 256; n += NTHR) {
        int j = n >> 2, g = n & 3;
        biasS[n] = bih[g * HDIM + j] + bhh[g * HDIM + j];
    }
    // ---- zero all A panels (covers pads + initial h = 0) ----------------
    for (int i = tid; i < 4 * 16384 / 16; i += NTHR)
        ((uint4*)(smem + OFF_AHI0))[i] = make_uint4(0, 0, 0, 0);

    // ---- B fill: row n'=4j+g, k: 0..27=Wih, 28..31=0, 32..95=Whh -------
    for (int idx = tid; idx < 256 * 96; idx += NTHR) {
        int n = idx / 96, k = idx % 96;
        int j = n >> 2, g = n & 3, orow = g * HDIM + j;
        float w = 0.0f;
        if (k < IDIM)      w = Wih[orow * IDIM + k];
        else if (k >= 32)  w = Whh[orow * HDIM + (k - 32)];
        int p  = k >> 6, kl = k & 63;
        uint32_t sw = SWZ((uint32_t)(n * 128 + kl * 2));
        uint16_t hb, lb; bsplit(w, hb, lb);
        *(uint16_t*)(smem + (p ? OFF_BHI1 : OFF_BHI0) + sw) = hb;
        *(uint16_t*)(smem + (p ? OFF_BLO1 : OFF_BLO0) + sw) = lb;
    }

    // ---- pair-local x mapping (t-invariant) + prefetch x_0 --------------
    // pair loads its own 16 rows: 16*28 = 448 elems, 64 threads -> 7 each
    const float* __restrict__ xb = x + (size_t)blockIdx.x * BT * TSTEPS * IDIM;
    int xoff[7];      // gmem offset (t=0); add t*28 per step
    int xsw[7];       // swizzled smem byte offset within A panel0
#pragma unroll
    for (int i = 0; i < 7; i++) {
        int idx  = ptid + i * 64;          // 0..447
        int brow = idx / IDIM, k = idx % IDIM;
        xoff[i] = (mw * 16 + brow) * (TSTEPS * IDIM) + k;
        xsw[i]  = (int)SWZ((uint32_t)((mw * 16 + brow) * 128 + k * 2));
    }
    float xr[7];
#pragma unroll
    for (int i = 0; i < 7; i++) xr[i] = xb[xoff[i]];

    // ---- per-thread GEMM/epilogue constants -----------------------------
    const int arow   = mw * 16 + (lane & 15);
    const int achunk = (lane >> 4) * 16;
    const int brow_l = ((lane >> 4) << 3) + (lane & 7);
    const int bchunk = ((lane >> 3) & 1) * 16;
    const int jpar = (lane & 3) >> 1;
    const int bown = mw * 16 + (lane >> 2) + ((lane & 1) << 3);
    const int jbase = 32 * nh;
    const uint32_t apan_hi_h = sb + (nh ? OFF_AHI1 : OFF_AHI0);  // h dest
    const uint32_t apan_lo_h = sb + (nh ? OFF_ALO1 : OFF_ALO0);

    float cs[16];
#pragma unroll
    for (int m = 0; m < 16; m++) cs[m] = 0.0f;

    float* hst = (float*)(smem + OFF_HST);       // dedicated staging

    __syncthreads();      // B, bias, zeroed A visible to all pairs

    for (int t = 0; t < TSTEPS; ++t) {
        // ---- write x_t into A panel0 cols 0..27 (pair rows only) --------
#pragma unroll
        for (int i = 0; i < 7; i++) {
            uint16_t hb, lb; bsplit(xr[i], hb, lb);
            *(uint16_t*)(smem + OFF_AHI0 + xsw[i]) = hb;
            *(uint16_t*)(smem + OFF_ALO0 + xsw[i]) = lb;
        }
        PAIR_BAR(barid);     // pair's x_t + h_t writes visible to pair

        // ---- GEMM: 6 k16 steps x 8 tile-pairs x 3 split products --------
        float d[16][4];
#pragma unroll
        for (int m = 0; m < 16; m++) {
            d[m][0] = 0.0f; d[m][1] = 0.0f; d[m][2] = 0.0f; d[m][3] = 0.0f;
        }
#pragma unroll
        for (int ks = 0; ks < 6; ks++) {
            const int p  = (ks < 4) ? 0 : 1;
            const int cb = (ks < 4) ? ks * 32 : (ks - 4) * 32;
            const uint32_t aswz = SWZ((uint32_t)(arow * 128 + cb + achunk));
            uint32_t ah[4], al[4];
            LDSM4(ah[0], ah[1], ah[2], ah[3],
                  sb + (p ? OFF_AHI1 : OFF_AHI0) + aswz);
            LDSM4(al[0], al[1], al[2], al[3],
                  sb + (p ? OFF_ALO1 : OFF_ALO0) + aswz);
#pragma unroll
            for (int g2 = 0; g2 < 8; g2++) {
                const int nb = nh * 128 + g2 * 16;
                const uint32_t bswz =
                    SWZ((uint32_t)((nb + brow_l) * 128 + cb + bchunk));
                uint32_t bhv[4], blv[4];
                LDSM4(bhv[0], bhv[1], bhv[2], bhv[3],
                      sb + (p ? OFF_BHI1 : OFF_BHI0) + bswz);
                LDSM4(blv[0], blv[1], blv[2], blv[3],
                      sb + (p ? OFF_BLO1 : OFF_BLO0) + bswz);
                MMA16816(d[2 * g2],     ah, bhv[0], bhv[1]);
                MMA16816(d[2 * g2],     ah, blv[0], blv[1]);
                MMA16816(d[2 * g2],     al, bhv[0], bhv[1]);
                MMA16816(d[2 * g2 + 1], ah, bhv[2], bhv[3]);
                MMA16816(d[2 * g2 + 1], ah, blv[2], blv[3]);
                MMA16816(d[2 * g2 + 1], al, bhv[2], bhv[3]);
            }
        }
        PAIR_BAR(barid);     // pair's A reads done before h/x overwrite

        // ---- prefetch x_{t+1} (overlaps epilogue) -----------------------
        if (t < TSTEPS - 1) {
#pragma unroll
            for (int i = 0; i < 7; i++)
                xr[i] = xb[xoff[i] + (t + 1) * IDIM];
        }

        // ---- epilogue: per n8-tile, shfl-exchange -> full LSTM unit -----
#pragma unroll
        for (int nt = 0; nt < 16; nt++) {
            float c0 = d[nt][0], c1 = d[nt][1], c2 = d[nt][2], c3 = d[nt][3];
            float s0 = (lane & 1) ? c0 : c2;
            float s1 = (lane & 1) ? c1 : c3;
            float r0 = __shfl_xor_sync(0xFFFFFFFFu, s0, 1);
            float r1 = __shfl_xor_sync(0xFFFFFFFFu, s1, 1);
            float gi, gf, gg, go;
            if (lane & 1) { gi = r0; gf = r1; gg = c2; go = c3; }
            else          { gi = c0; gf = c1; gg = r0; go = r1; }
            const int j = jbase + 2 * nt + jpar;
            float4 bb = *(const float4*)(biasS + 4 * j);
            float iv = sigf(gi + bb.x);
            float fv = sigf(gf + bb.y);
            float gv = tnhf(gg + bb.z);
            float ov = sigf(go + bb.w);
            float c  = fv * cs[nt] + iv * gv;
            cs[nt] = c;
            float h = ov * tnhf(c);
            // write h into A (panel chosen by j range) for next step
            const int colb = nh ? (4 * nt + 2 * jpar) : (64 + 4 * nt + 2 * jpar);
            const uint32_t sw = SWZ((uint32_t)(bown * 128 + colb));
            uint16_t hb, lb; bsplit(h, hb, lb);
            *(uint16_t*)((char*)smem + (apan_hi_h - sb) + sw) = hb;
            *(uint16_t*)((char*)smem + (apan_lo_h - sb) + sw) = lb;
            if (t == TSTEPS - 1) hst[bown * 65 + j] = h;   // stage for classifier
        }
    }
    __syncthreads();         // all pairs finished; hst complete

    // ---- classifier: out[b,cls] = b_cls + sum_j h[b,j]*Wcls[cls,j] ------
    const int bbase = blockIdx.x * BT;
    for (int idx = tid; idx < BT * 10; idx += NTHR) {
        int b = idx / 10, cls = idx % 10;
        float s = bcls[cls];
        const float* __restrict__ wc = Wcls + cls * HDIM;
#pragma unroll
        for (int j = 0; j < HDIM; j++) s += hst[b * 65 + j] * __ldg(&wc[j]);
        out[(size_t)(bbase + b) * 10 + cls] = s;
    }
}

extern "C" void kernel_launch(void* const* d_in, const int* in_sizes, int n_in,
                              void* d_out, int out_size) {
    const float* x    = (const float*)d_in[0];
    const float* Wih  = (const float*)d_in[1];
    const float* Whh  = (const float*)d_in[2];
    const float* bih  = (const float*)d_in[3];
    const float* bhh  = (const float*)d_in[4];
    const float* Wcls = (const float*)d_in[5];
    const float* bcls = (const float*)d_in[6];
    float* out = (float*)d_out;

    cudaFuncSetAttribute(lstm_mma_kernel,
                         cudaFuncAttributeMaxDynamicSharedMemorySize, SMEM_SZ);
    lstm_mma_kernel<<<16384 / BT, NTHR, SMEM_SZ>>>(x, Wih, Whh, bih, bhh,
                                                   Wcls, bcls, out);
}

// round 9
// speedup vs baseline: 2.1492x; 1.2327x over previous
#include <cuda_runtime.h>
#include <cuda_bf16.h>
#include <cstdint>

// LSTM (B=16384, T=28, I=28, H=64) + classifier via warp-level mma.sync bf16.
// One CTA = 128 batches, 1024 threads = 32 warps = 8 warp-QUADS; quad mw owns
// batch rows [16mw,16mw+16); warp nq (0..3) owns N-quarter (64 gate-rows).
// Per timestep per warp: D[16,64] = A[16,96] * Bq[64,96]^T,
// A=[x_t|pad|h], B gate-interleaved (row n=4j+g). fp32 accuracy via bf16
// split: D = Ah*Bh + Ah*Bl + Al*Bh (rel err ~2^-16). 8 warps/SMSP so tensor,
// MUFU and FMA phases of different warps overlap (fixes issue=35% @ 16 warps).

#define NTHR    1024
#define BT      128
#define TSTEPS  28
#define IDIM    28
#define HDIM    64

// SMEM layout (bytes). A panels: 128 rows x 64 bf16 cols (128B rows, SW128).
// B panels: 256 rows x 64 bf16 cols.
#define OFF_BIAS  0
#define OFF_AHI0  1024
#define OFF_AHI1  (OFF_AHI0 + 16384)
#define OFF_ALO0  (OFF_AHI1 + 16384)
#define OFF_ALO1  (OFF_ALO0 + 16384)
#define OFF_BHI0  (OFF_ALO1 + 16384)     // 66560
#define OFF_BHI1  (OFF_BHI0 + 32768)
#define OFF_BLO0  (OFF_BHI1 + 32768)
#define OFF_BLO1  (OFF_BLO0 + 32768)
#define OFF_HST   (OFF_BLO1 + 32768)     // 197632: 128 x 65 floats
#define SMEM_SZ   (OFF_HST + 128*65*4)   // 230912 (< 232448 cap)

#define SWZ(b) ((b) ^ (((b) >> 3) & 0x70))

static __device__ __forceinline__ uint32_t smem_u32(const void* p) {
    uint32_t a;
    asm("{ .reg .u64 t; cvta.to.shared.u64 t, %1; cvt.u32.u64 %0, t; }" : "=r"(a) : "l"(p));
    return a;
}
#define QUAD_BAR(ID)                                                         \
    asm volatile("bar.sync %0, 128;" :: "r"(ID) : "memory")
#define LDSM4(R0, R1, R2, R3, A)                                             \
    asm volatile("ldmatrix.sync.aligned.m8n8.x4.shared.b16 {%0,%1,%2,%3}, [%4];" \
                 : "=r"(R0), "=r"(R1), "=r"(R2), "=r"(R3) : "r"(A))
#define MMA16816(D, A, B0, B1)                                               \
    asm volatile("mma.sync.aligned.m16n8k16.row.col.f32.bf16.bf16.f32 "      \
                 "{%0,%1,%2,%3}, {%4,%5,%6,%7}, {%8,%9}, {%0,%1,%2,%3};"     \
                 : "+f"((D)[0]), "+f"((D)[1]), "+f"((D)[2]), "+f"((D)[3])    \
                 : "r"((A)[0]), "r"((A)[1]), "r"((A)[2]), "r"((A)[3]),       \
                   "r"(B0), "r"(B1))

static __device__ __forceinline__ float sigf(float v) {
    return __fdividef(1.0f, 1.0f + __expf(-v));
}
static __device__ __forceinline__ float tnhf(float v) {
    return 1.0f - 2.0f * __fdividef(1.0f, 1.0f + __expf(2.0f * v));
}
// bf16 split: v ~= hi + lo, each bf16 (combined rel err ~2^-16)
static __device__ __forceinline__ void bsplit(float v, uint16_t& hi, uint16_t& lo) {
    __nv_bfloat16 h = __float2bfloat16_rn(v);
    __nv_bfloat16 l = __float2bfloat16_rn(v - __bfloat162float(h));
    hi = __bfloat16_as_ushort(h);
    lo = __bfloat16_as_ushort(l);
}

__global__ void __launch_bounds__(NTHR, 1)
lstm_mma_kernel(const float* __restrict__ x,
                const float* __restrict__ Wih,   // [256,28]
                const float* __restrict__ Whh,   // [256,64]
                const float* __restrict__ bih,
                const float* __restrict__ bhh,
                const float* __restrict__ Wcls,  // [10,64]
                const float* __restrict__ bcls,  // [10]
                float* __restrict__ out)         // [B,10]
{
    extern __shared__ char smem[];
    const uint32_t sb = smem_u32(smem);
    const int tid  = threadIdx.x;
    const int wid  = tid >> 5;
    const int lane = tid & 31;
    const int mw   = wid >> 2;           // quad id: 16-row batch chunk
    const int nq   = wid & 3;            // N quarter (64 gate-rows)
    const int ptid = tid & 127;          // thread id within quad
    const int barid = mw + 1;            // named barrier (ids 1..8)
    float* biasS = (float*)(smem + OFF_BIAS);

    // ---- bias, gate-interleaved: biasS[4j+g] = bih[g*64+j]+bhh[...] -----
    if (tid < 256) {
        int j = tid >> 2, g = tid & 3;
        biasS[tid] = bih[g * HDIM + j] + bhh[g * HDIM + j];
    }
    // ---- zero all A panels (covers pads + initial h = 0) ----------------
    for (int i = tid; i < 4 * 16384 / 16; i += NTHR)
        ((uint4*)(smem + OFF_AHI0))[i] = make_uint4(0, 0, 0, 0);

    // ---- B fill: row n'=4j+g, k: 0..27=Wih, 28..31=0, 32..95=Whh -------
    for (int idx = tid; idx < 256 * 96; idx += NTHR) {
        int n = idx / 96, k = idx % 96;
        int j = n >> 2, g = n & 3, orow = g * HDIM + j;
        float w = 0.0f;
        if (k < IDIM)      w = Wih[orow * IDIM + k];
        else if (k >= 32)  w = Whh[orow * HDIM + (k - 32)];
        int p  = k >> 6, kl = k & 63;
        uint32_t sw = SWZ((uint32_t)(n * 128 + kl * 2));
        uint16_t hb, lb; bsplit(w, hb, lb);
        *(uint16_t*)(smem + (p ? OFF_BHI1 : OFF_BHI0) + sw) = hb;
        *(uint16_t*)(smem + (p ? OFF_BLO1 : OFF_BLO0) + sw) = lb;
    }

    // ---- quad-local x mapping (t-invariant) + prefetch x_0 --------------
    // quad loads its own 16 rows: 16*28 = 448 elems, 128 threads -> <=4 each
    const float* __restrict__ xb = x + (size_t)blockIdx.x * BT * TSTEPS * IDIM;
    int xoff[4], xsw[4];
#pragma unroll
    for (int i = 0; i < 4; i++) {
        int idx = ptid + i * 128;          // 0..511; valid < 448
        int brow = idx / IDIM, k = idx % IDIM;
        if (idx < 448) {
            xoff[i] = (mw * 16 + brow) * (TSTEPS * IDIM) + k;
            xsw[i]  = (int)SWZ((uint32_t)((mw * 16 + brow) * 128 + k * 2));
        } else { xoff[i] = -1; xsw[i] = 0; }
    }
    float xr[4];
#pragma unroll
    for (int i = 0; i < 4; i++) xr[i] = (xoff[i] >= 0) ? xb[xoff[i]] : 0.0f;

    // ---- per-thread GEMM/epilogue constants -----------------------------
    const int arow   = mw * 16 + (lane & 15);
    const int achunk = (lane >> 4) * 16;
    const int brow_l = ((lane >> 4) << 3) + (lane & 7);
    const int bchunk = ((lane >> 3) & 1) * 16;
    const int jpar = (lane & 3) >> 1;
    const int bown = mw * 16 + (lane >> 2) + ((lane & 1) << 3);
    const int jbase = 16 * nq;
    const int pan   = nq >> 1;                   // h panel for this quarter
    const int cbase = (nq & 1) * 32 + (pan ? 0 : 64);
    const uint32_t apan_hi_h = sb + (pan ? OFF_AHI1 : OFF_AHI0);
    const uint32_t apan_lo_h = sb + (pan ? OFF_ALO1 : OFF_ALO0);

    float cs[8];
#pragma unroll
    for (int m = 0; m < 8; m++) cs[m] = 0.0f;

    float* hst = (float*)(smem + OFF_HST);       // classifier staging

    __syncthreads();      // B, bias, zeroed A visible

    for (int t = 0; t < TSTEPS; ++t) {
        // ---- write x_t into A panel0 cols 0..27 (quad rows only) --------
#pragma unroll
        for (int i = 0; i < 4; i++) {
            if (xoff[i] >= 0) {
                uint16_t hb, lb; bsplit(xr[i], hb, lb);
                *(uint16_t*)(smem + OFF_AHI0 + xsw[i]) = hb;
                *(uint16_t*)(smem + OFF_ALO0 + xsw[i]) = lb;
            }
        }
        QUAD_BAR(barid);     // quad's x_t + h_t writes visible to quad

        // ---- GEMM: 6 k16 steps x 4 tile-pairs x 3 split products --------
        float d[8][4];
#pragma unroll
        for (int m = 0; m < 8; m++) {
            d[m][0] = 0.0f; d[m][1] = 0.0f; d[m][2] = 0.0f; d[m][3] = 0.0f;
        }
#pragma unroll
        for (int ks = 0; ks < 6; ks++) {
            const int p  = (ks < 4) ? 0 : 1;
            const int cb = (ks < 4) ? ks * 32 : (ks - 4) * 32;
            const uint32_t aswz = SWZ((uint32_t)(arow * 128 + cb + achunk));
            uint32_t ah[4], al[4];
            LDSM4(ah[0], ah[1], ah[2], ah[3],
                  sb + (p ? OFF_AHI1 : OFF_AHI0) + aswz);
            LDSM4(al[0], al[1], al[2], al[3],
                  sb + (p ? OFF_ALO1 : OFF_ALO0) + aswz);
#pragma unroll
            for (int g2 = 0; g2 < 4; g2++) {
                const int nb = nq * 64 + g2 * 16;
                const uint32_t bswz =
                    SWZ((uint32_t)((nb + brow_l) * 128 + cb + bchunk));
                uint32_t bhv[4], blv[4];
                LDSM4(bhv[0], bhv[1], bhv[2], bhv[3],
                      sb + (p ? OFF_BHI1 : OFF_BHI0) + bswz);
                LDSM4(blv[0], blv[1], blv[2], blv[3],
                      sb + (p ? OFF_BLO1 : OFF_BLO0) + bswz);
                MMA16816(d[2 * g2],     ah, bhv[0], bhv[1]);
                MMA16816(d[2 * g2],     ah, blv[0], blv[1]);
                MMA16816(d[2 * g2],     al, bhv[0], bhv[1]);
                MMA16816(d[2 * g2 + 1], ah, bhv[2], bhv[3]);
                MMA16816(d[2 * g2 + 1], ah, blv[2], blv[3]);
                MMA16816(d[2 * g2 + 1], al, bhv[2], bhv[3]);
            }
        }
        QUAD_BAR(barid);     // quad's A reads done before h/x overwrite

        // ---- prefetch x_{t+1} (overlaps epilogue) -----------------------
        if (t < TSTEPS - 1) {
#pragma unroll
            for (int i = 0; i < 4; i++)
                if (xoff[i] >= 0) xr[i] = xb[xoff[i] + (t + 1) * IDIM];
        }

        // ---- epilogue: per n8-tile, shfl-exchange -> full LSTM unit -----
#pragma unroll
        for (int nt = 0; nt < 8; nt++) {
            float c0 = d[nt][0], c1 = d[nt][1], c2 = d[nt][2], c3 = d[nt][3];
            float s0 = (lane & 1) ? c0 : c2;
            float s1 = (lane & 1) ? c1 : c3;
            float r0 = __shfl_xor_sync(0xFFFFFFFFu, s0, 1);
            float r1 = __shfl_xor_sync(0xFFFFFFFFu, s1, 1);
            float gi, gf, gg, go;
            if (lane & 1) { gi = r0; gf = r1; gg = c2; go = c3; }
            else          { gi = c0; gf = c1; gg = r0; go = r1; }
            const int j = jbase + 2 * nt + jpar;
            float4 bb = *(const float4*)(biasS + 4 * j);
            float iv = sigf(gi + bb.x);
            float fv = sigf(gf + bb.y);
            float gv = tnhf(gg + bb.z);
            float ov = sigf(go + bb.w);
            float c  = fv * cs[nt] + iv * gv;
            cs[nt] = c;
            float h = ov * tnhf(c);
            // write h into A (panel chosen by j range) for next step
            const int colb = cbase + 4 * nt + 2 * jpar;
            const uint32_t sw = SWZ((uint32_t)(bown * 128 + colb));
            uint16_t hb, lb; bsplit(h, hb, lb);
            *(uint16_t*)((char*)smem + (apan_hi_h - sb) + sw) = hb;
            *(uint16_t*)((char*)smem + (apan_lo_h - sb) + sw) = lb;
            if (t == TSTEPS - 1) hst[bown * 65 + j] = h;   // stage for classifier
        }
    }
    __syncthreads();         // all quads finished; hst complete

    // ---- classifier: out[b,cls] = b_cls + sum_j h[b,j]*Wcls[cls,j] ------
    const int bbase = blockIdx.x * BT;
    for (int idx = tid; idx < BT * 10; idx += NTHR) {
        int b = idx / 10, cls = idx % 10;
        float s = bcls[cls];
        const float* __restrict__ wc = Wcls + cls * HDIM;
#pragma unroll
        for (int j = 0; j < HDIM; j++) s += hst[b * 65 + j] * __ldg(&wc[j]);
        out[(size_t)(bbase + b) * 10 + cls] = s;
    }
}

extern "C" void kernel_launch(void* const* d_in, const int* in_sizes, int n_in,
                              void* d_out, int out_size) {
    const float* x    = (const float*)d_in[0];
    const float* Wih  = (const float*)d_in[1];
    const float* Whh  = (const float*)d_in[2];
    const float* bih  = (const float*)d_in[3];
    const float* bhh  = (const float*)d_in[4];
    const float* Wcls = (const float*)d_in[5];
    const float* bcls = (const float*)d_in[6];
    float* out = (float*)d_out;

    cudaFuncSetAttribute(lstm_mma_kernel,
                         cudaFuncAttributeMaxDynamicSharedMemorySize, SMEM_SZ);
    lstm_mma_kernel<<<16384 / BT, NTHR, SMEM_SZ>>>(x, Wih, Whh, bih, bhh,
                                                   Wcls, bcls, out);
}

// round 10
// speedup vs baseline: 2.4946x; 1.1607x over previous
#include <cuda_runtime.h>
#include <cuda_fp16.h>
#include <cstdint>

// LSTM (B=16384, T=28, I=28, H=64) + classifier via warp-level mma.sync fp16.
// One CTA = 128 batches, 1024 threads = 32 warps = 8 warp-QUADS; quad mw owns
// batch rows [16mw,16mw+16); warp nq (0..3) owns N-quarter (64 gate-rows).
// Numerics: A = [x_t|pad|h] as 2-term fp16 split (eff ~2^-22, protects the
// recurrent h path), B = weights as SINGLE fp16 (2^-12 quantization, static).
// D = Ah*B + Al*B, fp32 accumulate -> 2 MMA products (vs 3 for bf16 split),
// and half the B SMEM traffic (L1 port was 66.7% = binding pipe in R9).

#define NTHR    1024
#define BT      128
#define TSTEPS  28
#define IDIM    28
#define HDIM    64

// SMEM layout (bytes). A panels: 128 rows x 64 fp16 cols (128B rows, SW128).
// B panels: 256 rows x 64 fp16 cols (single precision level, no lo).
#define OFF_BIAS  0
#define OFF_AHI0  1024
#define OFF_AHI1  (OFF_AHI0 + 16384)
#define OFF_ALO0  (OFF_AHI1 + 16384)
#define OFF_ALO1  (OFF_ALO0 + 16384)
#define OFF_B0    (OFF_ALO1 + 16384)     // 66560
#define OFF_B1    (OFF_B0 + 32768)       // 99328
#define OFF_HST   (OFF_B1 + 32768)       // 132096: 128 x 65 floats
#define SMEM_SZ   (OFF_HST + 128*65*4)   // 165376

#define SWZ(b) ((b) ^ (((b) >> 3) & 0x70))

static __device__ __forceinline__ uint32_t smem_u32(const void* p) {
    uint32_t a;
    asm("{ .reg .u64 t; cvta.to.shared.u64 t, %1; cvt.u32.u64 %0, t; }" : "=r"(a) : "l"(p));
    return a;
}
#define QUAD_BAR(ID)                                                         \
    asm volatile("bar.sync %0, 128;" :: "r"(ID) : "memory")
#define LDSM4(R0, R1, R2, R3, A)                                             \
    asm volatile("ldmatrix.sync.aligned.m8n8.x4.shared.b16 {%0,%1,%2,%3}, [%4];" \
                 : "=r"(R0), "=r"(R1), "=r"(R2), "=r"(R3) : "r"(A))
#define MMA16816(D, A, B0, B1)                                               \
    asm volatile("mma.sync.aligned.m16n8k16.row.col.f32.f16.f16.f32 "        \
                 "{%0,%1,%2,%3}, {%4,%5,%6,%7}, {%8,%9}, {%0,%1,%2,%3};"     \
                 : "+f"((D)[0]), "+f"((D)[1]), "+f"((D)[2]), "+f"((D)[3])    \
                 : "r"((A)[0]), "r"((A)[1]), "r"((A)[2]), "r"((A)[3]),       \
                   "r"(B0), "r"(B1))

static __device__ __forceinline__ float sigf(float v) {
    return __fdividef(1.0f, 1.0f + __expf(-v));
}
static __device__ __forceinline__ float tnhf(float v) {
    return 1.0f - 2.0f * __fdividef(1.0f, 1.0f + __expf(2.0f * v));
}
// fp16 split: v ~= hi + lo, each fp16 (combined ~22 mantissa bits)
static __device__ __forceinline__ void hsplit(float v, uint16_t& hi, uint16_t& lo) {
    __half h = __float2half_rn(v);
    __half l = __float2half_rn(v - __half2float(h));
    hi = __half_as_ushort(h);
    lo = __half_as_ushort(l);
}

__global__ void __launch_bounds__(NTHR, 1)
lstm_mma_kernel(const float* __restrict__ x,
                const float* __restrict__ Wih,   // [256,28]
                const float* __restrict__ Whh,   // [256,64]
                const float* __restrict__ bih,
                const float* __restrict__ bhh,
                const float* __restrict__ Wcls,  // [10,64]
                const float* __restrict__ bcls,  // [10]
                float* __restrict__ out)         // [B,10]
{
    extern __shared__ char smem[];
    const uint32_t sb = smem_u32(smem);
    const int tid  = threadIdx.x;
    const int wid  = tid >> 5;
    const int lane = tid & 31;
    const int mw   = wid >> 2;           // quad id: 16-row batch chunk
    const int nq   = wid & 3;            // N quarter (64 gate-rows)
    const int ptid = tid & 127;          // thread id within quad
    const int barid = mw + 1;            // named barrier (ids 1..8)
    float* biasS = (float*)(smem + OFF_BIAS);

    // ---- bias, gate-interleaved: biasS[4j+g] = bih[g*64+j]+bhh[...] -----
    if (tid < 256) {
        int j = tid >> 2, g = tid & 3;
        biasS[tid] = bih[g * HDIM + j] + bhh[g * HDIM + j];
    }
    // ---- zero all A panels (covers pads + initial h = 0) ----------------
    for (int i = tid; i < 4 * 16384 / 16; i += NTHR)
        ((uint4*)(smem + OFF_AHI0))[i] = make_uint4(0, 0, 0, 0);

    // ---- B fill (single fp16): row n'=4j+g, k: 0..27=Wih, 28..31=0,
    //      32..95=Whh; panel0 = k 0..63, panel1 = k 64..95 --------------
    for (int idx = tid; idx < 256 * 96; idx += NTHR) {
        int n = idx / 96, k = idx % 96;
        int j = n >> 2, g = n & 3, orow = g * HDIM + j;
        float w = 0.0f;
        if (k < IDIM)      w = Wih[orow * IDIM + k];
        else if (k >= 32)  w = Whh[orow * HDIM + (k - 32)];
        int p  = k >> 6, kl = k & 63;
        uint32_t sw = SWZ((uint32_t)(n * 128 + kl * 2));
        *(uint16_t*)(smem + (p ? OFF_B1 : OFF_B0) + sw) =
            __half_as_ushort(__float2half_rn(w));
    }
    // zero pad cols of B panel1 (k 96..127 region = kl 32..63)
    for (int idx = tid; idx < 256 * 32; idx += NTHR) {
        int n = idx >> 5, kl = 32 + (idx & 31);
        uint32_t sw = SWZ((uint32_t)(n * 128 + kl * 2));
        *(uint16_t*)(smem + OFF_B1 + sw) = 0;
    }

    // ---- quad-local x mapping (t-invariant) + prefetch x_0 --------------
    const float* __restrict__ xb = x + (size_t)blockIdx.x * BT * TSTEPS * IDIM;
    int xoff[4], xsw[4];
#pragma unroll
    for (int i = 0; i < 4; i++) {
        int idx = ptid + i * 128;          // 0..511; valid < 448
        int brow = idx / IDIM, k = idx % IDIM;
        if (idx < 448) {
            xoff[i] = (mw * 16 + brow) * (TSTEPS * IDIM) + k;
            xsw[i]  = (int)SWZ((uint32_t)((mw * 16 + brow) * 128 + k * 2));
        } else { xoff[i] = -1; xsw[i] = 0; }
    }
    float xr[4];
#pragma unroll
    for (int i = 0; i < 4; i++) xr[i] = (xoff[i] >= 0) ? xb[xoff[i]] : 0.0f;

    // ---- per-thread GEMM/epilogue constants -----------------------------
    const int arow   = mw * 16 + (lane & 15);
    const int achunk = (lane >> 4) * 16;
    const int brow_l = ((lane >> 4) << 3) + (lane & 7);
    const int bchunk = ((lane >> 3) & 1) * 16;
    const int jpar = (lane & 3) >> 1;
    const int bown = mw * 16 + (lane >> 2) + ((lane & 1) << 3);
    const int jbase = 16 * nq;
    const int pan   = nq >> 1;                   // h panel for this quarter
    const int cbase = (nq & 1) * 32 + (pan ? 0 : 64);
    const uint32_t apan_hi_h = sb + (pan ? OFF_AHI1 : OFF_AHI0);
    const uint32_t apan_lo_h = sb + (pan ? OFF_ALO1 : OFF_ALO0);

    float cs[8];
#pragma unroll
    for (int m = 0; m < 8; m++) cs[m] = 0.0f;

    float* hst = (float*)(smem + OFF_HST);       // classifier staging

    __syncthreads();      // B, bias, zeroed A visible

    for (int t = 0; t < TSTEPS; ++t) {
        // ---- write x_t into A panel0 cols 0..27 (quad rows only) --------
#pragma unroll
        for (int i = 0; i < 4; i++) {
            if (xoff[i] >= 0) {
                uint16_t hb, lb; hsplit(xr[i], hb, lb);
                *(uint16_t*)(smem + OFF_AHI0 + xsw[i]) = hb;
                *(uint16_t*)(smem + OFF_ALO0 + xsw[i]) = lb;
            }
        }
        QUAD_BAR(barid);     // quad's x_t + h_t writes visible to quad

        // ---- GEMM: 6 k16 steps x 4 tile-pairs x 2 split products --------
        float d[8][4];
#pragma unroll
        for (int m = 0; m < 8; m++) {
            d[m][0] = 0.0f; d[m][1] = 0.0f; d[m][2] = 0.0f; d[m][3] = 0.0f;
        }
#pragma unroll
        for (int ks = 0; ks < 6; ks++) {
            const int p  = (ks < 4) ? 0 : 1;
            const int cb = (ks < 4) ? ks * 32 : (ks - 4) * 32;
            const uint32_t aswz = SWZ((uint32_t)(arow * 128 + cb + achunk));
            uint32_t ah[4], al[4];
            LDSM4(ah[0], ah[1], ah[2], ah[3],
                  sb + (p ? OFF_AHI1 : OFF_AHI0) + aswz);
            LDSM4(al[0], al[1], al[2], al[3],
                  sb + (p ? OFF_ALO1 : OFF_ALO0) + aswz);
#pragma unroll
            for (int g2 = 0; g2 < 4; g2++) {
                const int nb = nq * 64 + g2 * 16;
                const uint32_t bswz =
                    SWZ((uint32_t)((nb + brow_l) * 128 + cb + bchunk));
                uint32_t bv[4];
                LDSM4(bv[0], bv[1], bv[2], bv[3],
                      sb + (p ? OFF_B1 : OFF_B0) + bswz);
                MMA16816(d[2 * g2],     ah, bv[0], bv[1]);
                MMA16816(d[2 * g2],     al, bv[0], bv[1]);
                MMA16816(d[2 * g2 + 1], ah, bv[2], bv[3]);
                MMA16816(d[2 * g2 + 1], al, bv[2], bv[3]);
            }
        }
        QUAD_BAR(barid);     // quad's A reads done before h/x overwrite

        // ---- prefetch x_{t+1} (overlaps epilogue) -----------------------
        if (t < TSTEPS - 1) {
#pragma unroll
            for (int i = 0; i < 4; i++)
                if (xoff[i] >= 0) xr[i] = xb[xoff[i] + (t + 1) * IDIM];
        }

        // ---- epilogue: per n8-tile, shfl-exchange -> full LSTM unit -----
#pragma unroll
        for (int nt = 0; nt < 8; nt++) {
            float c0 = d[nt][0], c1 = d[nt][1], c2 = d[nt][2], c3 = d[nt][3];
            float s0 = (lane & 1) ? c0 : c2;
            float s1 = (lane & 1) ? c1 : c3;
            float r0 = __shfl_xor_sync(0xFFFFFFFFu, s0, 1);
            float r1 = __shfl_xor_sync(0xFFFFFFFFu, s1, 1);
            float gi, gf, gg, go;
            if (lane & 1) { gi = r0; gf = r1; gg = c2; go = c3; }
            else          { gi = c0; gf = c1; gg = r0; go = r1; }
            const int j = jbase + 2 * nt + jpar;
            float4 bb = *(const float4*)(biasS + 4 * j);
            float iv = sigf(gi + bb.x);
            float fv = sigf(gf + bb.y);
            float gv = tnhf(gg + bb.z);
            float ov = sigf(go + bb.w);
            float c  = fv * cs[nt] + iv * gv;
            cs[nt] = c;
            float h = ov * tnhf(c);
            // write h into A (panel chosen by j range) for next step
            const int colb = cbase + 4 * nt + 2 * jpar;
            const uint32_t sw = SWZ((uint32_t)(bown * 128 + colb));
            uint16_t hb, lb; hsplit(h, hb, lb);
            *(uint16_t*)((char*)smem + (apan_hi_h - sb) + sw) = hb;
            *(uint16_t*)((char*)smem + (apan_lo_h - sb) + sw) = lb;
            if (t == TSTEPS - 1) hst[bown * 65 + j] = h;   // stage for classifier
        }
    }
    __syncthreads();         // all quads finished; hst complete

    // ---- classifier: out[b,cls] = b_cls + sum_j h[b,j]*Wcls[cls,j] ------
    const int bbase = blockIdx.x * BT;
    for (int idx = tid; idx < BT * 10; idx += NTHR) {
        int b = idx / 10, cls = idx % 10;
        float s = bcls[cls];
        const float* __restrict__ wc = Wcls + cls * HDIM;
#pragma unroll
        for (int j = 0; j < HDIM; j++) s += hst[b * 65 + j] * __ldg(&wc[j]);
        out[(size_t)(bbase + b) * 10 + cls] = s;
    }
}

extern "C" void kernel_launch(void* const* d_in, const int* in_sizes, int n_in,
                              void* d_out, int out_size) {
    const float* x    = (const float*)d_in[0];
    const float* Wih  = (const float*)d_in[1];
    const float* Whh  = (const float*)d_in[2];
    const float* bih  = (const float*)d_in[3];
    const float* bhh  = (const float*)d_in[4];
    const float* Wcls = (const float*)d_in[5];
    const float* bcls = (const float*)d_in[6];
    float* out = (float*)d_out;

    cudaFuncSetAttribute(lstm_mma_kernel,
                         cudaFuncAttributeMaxDynamicSharedMemorySize, SMEM_SZ);
    lstm_mma_kernel<<<16384 / BT, NTHR, SMEM_SZ>>>(x, Wih, Whh, bih, bhh,
                                                   Wcls, bcls, out);
}

// round 11
// speedup vs baseline: 2.9982x; 1.2019x over previous
#include <cuda_runtime.h>
#include <cuda_fp16.h>
#include <cstdint>

// LSTM (B=16384, T=28, I=28, H=64) + classifier via warp-level mma.sync fp16.
// One CTA = 128 batches, 1024 threads = 32 warps = 8 warp-QUADS; quad mw owns
// batch rows [16mw,16mw+16); warp nq (0..3) owns N-quarter (64 gate-rows).
// Numerics: A = [x_t|pad|h] and B = weights all SINGLE fp16 (2^-11 roundoff).
// R10 measured rel_err=1.1e-4 with exact A + fp16 B -> fp16 h adds ~sqrt(2)x,
// well under the 1e-3 gate. D = A*B with fp32 accumulate: 48 MMAs/warp/step
// (half of R10), A LDSM traffic halved. Activations stay exact (EX2/RCP).

#define NTHR    1024
#define BT      128
#define TSTEPS  28
#define IDIM    28
#define HDIM    64

// SMEM layout (bytes). A panels: 128 rows x 64 fp16 cols (128B rows, SW128).
// B panels: 256 rows x 64 fp16 cols.
#define OFF_BIAS  0
#define OFF_A0    1024
#define OFF_A1    (OFF_A0 + 16384)       // 17408
#define OFF_B0    (OFF_A1 + 16384)       // 33792
#define OFF_B1    (OFF_B0 + 32768)       // 66560
#define OFF_HST   (OFF_B1 + 32768)       // 99328: 128 x 65 floats
#define SMEM_SZ   (OFF_HST + 128*65*4)   // 132608

#define SWZ(b) ((b) ^ (((b) >> 3) & 0x70))

static __device__ __forceinline__ uint32_t smem_u32(const void* p) {
    uint32_t a;
    asm("{ .reg .u64 t; cvta.to.shared.u64 t, %1; cvt.u32.u64 %0, t; }" : "=r"(a) : "l"(p));
    return a;
}
#define QUAD_BAR(ID)                                                         \
    asm volatile("bar.sync %0, 128;" :: "r"(ID) : "memory")
#define LDSM4(R0, R1, R2, R3, A)                                             \
    asm volatile("ldmatrix.sync.aligned.m8n8.x4.shared.b16 {%0,%1,%2,%3}, [%4];" \
                 : "=r"(R0), "=r"(R1), "=r"(R2), "=r"(R3) : "r"(A))
#define MMA16816(D, A, B0, B1)                                               \
    asm volatile("mma.sync.aligned.m16n8k16.row.col.f32.f16.f16.f32 "        \
                 "{%0,%1,%2,%3}, {%4,%5,%6,%7}, {%8,%9}, {%0,%1,%2,%3};"     \
                 : "+f"((D)[0]), "+f"((D)[1]), "+f"((D)[2]), "+f"((D)[3])    \
                 : "r"((A)[0]), "r"((A)[1]), "r"((A)[2]), "r"((A)[3]),       \
                   "r"(B0), "r"(B1))

static __device__ __forceinline__ float sigf(float v) {
    return __fdividef(1.0f, 1.0f + __expf(-v));
}
static __device__ __forceinline__ float tnhf(float v) {
    return 1.0f - 2.0f * __fdividef(1.0f, 1.0f + __expf(2.0f * v));
}

__global__ void __launch_bounds__(NTHR, 1)
lstm_mma_kernel(const float* __restrict__ x,
                const float* __restrict__ Wih,   // [256,28]
                const float* __restrict__ Whh,   // [256,64]
                const float* __restrict__ bih,
                const float* __restrict__ bhh,
                const float* __restrict__ Wcls,  // [10,64]
                const float* __restrict__ bcls,  // [10]
                float* __restrict__ out)         // [B,10]
{
    extern __shared__ char smem[];
    const uint32_t sb = smem_u32(smem);
    const int tid  = threadIdx.x;
    const int wid  = tid >> 5;
    const int lane = tid & 31;
    const int mw   = wid >> 2;           // quad id: 16-row batch chunk
    const int nq   = wid & 3;            // N quarter (64 gate-rows)
    const int ptid = tid & 127;          // thread id within quad
    const int barid = mw + 1;            // named barrier (ids 1..8)
    float* biasS = (float*)(smem + OFF_BIAS);

    // ---- bias, gate-interleaved: biasS[4j+g] = bih[g*64+j]+bhh[...] -----
    if (tid < 256) {
        int j = tid >> 2, g = tid & 3;
        biasS[tid] = bih[g * HDIM + j] + bhh[g * HDIM + j];
    }
    // ---- zero A panels (covers pads + initial h = 0) --------------------
    for (int i = tid; i < 2 * 16384 / 16; i += NTHR)
        ((uint4*)(smem + OFF_A0))[i] = make_uint4(0, 0, 0, 0);

    // ---- B fill (single fp16): row n'=4j+g, k: 0..27=Wih, 28..31=0,
    //      32..95=Whh; panel0 = k 0..63, panel1 = k 64..95 ---------------
    for (int idx = tid; idx < 256 * 96; idx += NTHR) {
        int n = idx / 96, k = idx % 96;
        int j = n >> 2, g = n & 3, orow = g * HDIM + j;
        float w = 0.0f;
        if (k < IDIM)      w = Wih[orow * IDIM + k];
        else if (k >= 32)  w = Whh[orow * HDIM + (k - 32)];
        int p  = k >> 6, kl = k & 63;
        uint32_t sw = SWZ((uint32_t)(n * 128 + kl * 2));
        *(uint16_t*)(smem + (p ? OFF_B1 : OFF_B0) + sw) =
            __half_as_ushort(__float2half_rn(w));
    }
    // zero unused cols of B panel1 (kl 32..63)
    for (int idx = tid; idx < 256 * 32; idx += NTHR) {
        int n = idx >> 5, kl = 32 + (idx & 31);
        uint32_t sw = SWZ((uint32_t)(n * 128 + kl * 2));
        *(uint16_t*)(smem + OFF_B1 + sw) = 0;
    }

    // ---- quad-local x mapping (t-invariant) + prefetch x_0 --------------
    const float* __restrict__ xb = x + (size_t)blockIdx.x * BT * TSTEPS * IDIM;
    int xoff[4], xsw[4];
#pragma unroll
    for (int i = 0; i < 4; i++) {
        int idx = ptid + i * 128;          // 0..511; valid < 448
        int brow = idx / IDIM, k = idx % IDIM;
        if (idx < 448) {
            xoff[i] = (mw * 16 + brow) * (TSTEPS * IDIM) + k;
            xsw[i]  = (int)SWZ((uint32_t)((mw * 16 + brow) * 128 + k * 2));
        } else { xoff[i] = -1; xsw[i] = 0; }
    }
    float xr[4];
#pragma unroll
    for (int i = 0; i < 4; i++) xr[i] = (xoff[i] >= 0) ? xb[xoff[i]] : 0.0f;

    // ---- per-thread GEMM/epilogue constants -----------------------------
    const int arow   = mw * 16 + (lane & 15);
    const int achunk = (lane >> 4) * 16;
    const int brow_l = ((lane >> 4) << 3) + (lane & 7);
    const int bchunk = ((lane >> 3) & 1) * 16;
    const int jpar = (lane & 3) >> 1;
    const int bown = mw * 16 + (lane >> 2) + ((lane & 1) << 3);
    const int jbase = 16 * nq;
    const int pan   = nq >> 1;                   // h panel for this quarter
    const int cbase = (nq & 1) * 32 + (pan ? 0 : 64);
    const uint32_t apan_h = sb + (pan ? OFF_A1 : OFF_A0);

    float cs[8];
#pragma unroll
    for (int m = 0; m < 8; m++) cs[m] = 0.0f;

    float* hst = (float*)(smem + OFF_HST);       // classifier staging

    __syncthreads();      // B, bias, zeroed A visible

    for (int t = 0; t < TSTEPS; ++t) {
        // ---- write x_t into A panel0 cols 0..27 (quad rows only) --------
#pragma unroll
        for (int i = 0; i < 4; i++) {
            if (xoff[i] >= 0) {
                *(uint16_t*)(smem + OFF_A0 + xsw[i]) =
                    __half_as_ushort(__float2half_rn(xr[i]));
            }
        }
        QUAD_BAR(barid);     // quad's x_t + h_t writes visible to quad

        // ---- GEMM: 6 k16 steps x 4 tile-pairs, single product -----------
        float d[8][4];
#pragma unroll
        for (int m = 0; m < 8; m++) {
            d[m][0] = 0.0f; d[m][1] = 0.0f; d[m][2] = 0.0f; d[m][3] = 0.0f;
        }
#pragma unroll
        for (int ks = 0; ks < 6; ks++) {
            const int p  = (ks < 4) ? 0 : 1;
            const int cb = (ks < 4) ? ks * 32 : (ks - 4) * 32;
            const uint32_t aswz = SWZ((uint32_t)(arow * 128 + cb + achunk));
            uint32_t av[4];
            LDSM4(av[0], av[1], av[2], av[3],
                  sb + (p ? OFF_A1 : OFF_A0) + aswz);
#pragma unroll
            for (int g2 = 0; g2 < 4; g2++) {
                const int nb = nq * 64 + g2 * 16;
                const uint32_t bswz =
                    SWZ((uint32_t)((nb + brow_l) * 128 + cb + bchunk));
                uint32_t bv[4];
                LDSM4(bv[0], bv[1], bv[2], bv[3],
                      sb + (p ? OFF_B1 : OFF_B0) + bswz);
                MMA16816(d[2 * g2],     av, bv[0], bv[1]);
                MMA16816(d[2 * g2 + 1], av, bv[2], bv[3]);
            }
        }
        QUAD_BAR(barid);     // quad's A reads done before h/x overwrite

        // ---- prefetch x_{t+1} (overlaps epilogue) -----------------------
        if (t < TSTEPS - 1) {
#pragma unroll
            for (int i = 0; i < 4; i++)
                if (xoff[i] >= 0) xr[i] = xb[xoff[i] + (t + 1) * IDIM];
        }

        // ---- epilogue: per n8-tile, shfl-exchange -> full LSTM unit -----
#pragma unroll
        for (int nt = 0; nt < 8; nt++) {
            float c0 = d[nt][0], c1 = d[nt][1], c2 = d[nt][2], c3 = d[nt][3];
            float s0 = (lane & 1) ? c0 : c2;
            float s1 = (lane & 1) ? c1 : c3;
            float r0 = __shfl_xor_sync(0xFFFFFFFFu, s0, 1);
            float r1 = __shfl_xor_sync(0xFFFFFFFFu, s1, 1);
            float gi, gf, gg, go;
            if (lane & 1) { gi = r0; gf = r1; gg = c2; go = c3; }
            else          { gi = c0; gf = c1; gg = r0; go = r1; }
            const int j = jbase + 2 * nt + jpar;
            float4 bb = *(const float4*)(biasS + 4 * j);
            float iv = sigf(gi + bb.x);
            float fv = sigf(gf + bb.y);
            float gv = tnhf(gg + bb.z);
            float ov = sigf(go + bb.w);
            float c  = fv * cs[nt] + iv * gv;
            cs[nt] = c;
            float h = ov * tnhf(c);
            // write h (single fp16) into A for next step
            const int colb = cbase + 4 * nt + 2 * jpar;
            const uint32_t sw = SWZ((uint32_t)(bown * 128 + colb));
            *(uint16_t*)((char*)smem + (apan_h - sb) + sw) =
                __half_as_ushort(__float2half_rn(h));
            if (t == TSTEPS - 1) hst[bown * 65 + j] = h;   // stage for classifier
        }
    }
    __syncthreads();         // all quads finished; hst complete

    // ---- classifier: out[b,cls] = b_cls + sum_j h[b,j]*Wcls[cls,j] ------
    const int bbase = blockIdx.x * BT;
    for (int idx = tid; idx < BT * 10; idx += NTHR) {
        int b = idx / 10, cls = idx % 10;
        float s = bcls[cls];
        const float* __restrict__ wc = Wcls + cls * HDIM;
#pragma unroll
        for (int j = 0; j < HDIM; j++) s += hst[b * 65 + j] * __ldg(&wc[j]);
        out[(size_t)(bbase + b) * 10 + cls] = s;
    }
}

extern "C" void kernel_launch(void* const* d_in, const int* in_sizes, int n_in,
                              void* d_out, int out_size) {
    const float* x    = (const float*)d_in[0];
    const float* Wih  = (const float*)d_in[1];
    const float* Whh  = (const float*)d_in[2];
    const float* bih  = (const float*)d_in[3];
    const float* bhh  = (const float*)d_in[4];
    const float* Wcls = (const float*)d_in[5];
    const float* bcls = (const float*)d_in[6];
    float* out = (float*)d_out;

    cudaFuncSetAttribute(lstm_mma_kernel,
                         cudaFuncAttributeMaxDynamicSharedMemorySize, SMEM_SZ);
    lstm_mma_kernel<<<16384 / BT, NTHR, SMEM_SZ>>>(x, Wih, Whh, bih, bhh,
                                                   Wcls, bcls, out);
}

// round 13
// speedup vs baseline: 3.9866x; 1.3297x over previous
#include <cuda_runtime.h>
#include <cuda_fp16.h>
#include <cstdint>

// LSTM (B=16384, T=28, I=28, H=64) + classifier via warp-level mma.sync fp16.
// One CTA = 128 batches, 1024 threads = 32 warps = 8 warp-QUADS; quad mw owns
// batch rows [16mw,16mw+16); warp nq (0..3) owns N-quarter (64 gate-rows).
// B row layout (tile-PAIR gate packing): for unit j, gates live in an n8-tile
// pair -- even tile rows [i,f] x 4 units, odd tile [g,o] x 4 units -- so the
// mma D-fragment gives each thread ALL 4 gates of its unit: no shfl exchange.
// Bias rides in the GEMM as A col 28 = 1.0, B col 28 = bih+bhh.
// Activations via tanh.approx (sigmoid = 0.5*tanh(x/2)+0.5): 5 MUFU/unit
// instead of 10 (MUFU was the dominant hidden serial cost in R11).

#define NTHR    1024
#define BT      128
#define TSTEPS  28
#define IDIM    28
#define HDIM    64

// SMEM layout (bytes). A panels: 128 rows x 64 fp16 cols (128B rows, SW128).
// B panels: 256 rows x 64 fp16 cols.
#define OFF_A0    0
#define OFF_A1    16384
#define OFF_B0    32768
#define OFF_B1    65536
#define OFF_HST   98304                  // 128 x 65 floats
#define SMEM_SZ   (OFF_HST + 128*65*4)   // 131584

#define SWZ(b) ((b) ^ (((b) >> 3) & 0x70))

static __device__ __forceinline__ uint32_t smem_u32(const void* p) {
    uint32_t a;
    asm("{ .reg .u64 t; cvta.to.shared.u64 t, %1; cvt.u32.u64 %0, t; }" : "=r"(a) : "l"(p));
    return a;
}
#define QUAD_BAR(ID)                                                         \
    asm volatile("bar.sync %0, 128;" :: "r"(ID) : "memory")
#define LDSM4(R0, R1, R2, R3, A)                                             \
    asm volatile("ldmatrix.sync.aligned.m8n8.x4.shared.b16 {%0,%1,%2,%3}, [%4];" \
                 : "=r"(R0), "=r"(R1), "=r"(R2), "=r"(R3) : "r"(A))
#define MMA16816(D, A, B0, B1)                                               \
    asm volatile("mma.sync.aligned.m16n8k16.row.col.f32.f16.f16.f32 "        \
                 "{%0,%1,%2,%3}, {%4,%5,%6,%7}, {%8,%9}, {%0,%1,%2,%3};"     \
                 : "+f"((D)[0]), "+f"((D)[1]), "+f"((D)[2]), "+f"((D)[3])    \
                 : "r"((A)[0]), "r"((A)[1]), "r"((A)[2]), "r"((A)[3]),       \
                   "r"(B0), "r"(B1))

static __device__ __forceinline__ float tanhap(float v) {
    float r; asm("tanh.approx.f32 %0, %1;" : "=f"(r) : "f"(v)); return r;
}
static __device__ __forceinline__ float sigap(float v) {
    return fmaf(0.5f, tanhap(0.5f * v), 0.5f);
}

__global__ void __launch_bounds__(NTHR, 1)
lstm_mma_kernel(const float* __restrict__ x,
                const float* __restrict__ Wih,   // [256,28]
                const float* __restrict__ Whh,   // [256,64]
                const float* __restrict__ bih,
                const float* __restrict__ bhh,
                const float* __restrict__ Wcls,  // [10,64]
                const float* __restrict__ bcls,  // [10]
                float* __restrict__ out)         // [B,10]
{
    extern __shared__ char smem[];
    const uint32_t sb = smem_u32(smem);
    const int tid  = threadIdx.x;
    const int wid  = tid >> 5;
    const int lane = tid & 31;
    const int mw   = wid >> 2;           // quad id: 16-row batch chunk
    const int nq   = wid & 3;            // N quarter (64 gate-rows, 16 units)
    const int ptid = tid & 127;          // thread id within quad
    const int barid = mw + 1;            // named barrier (ids 1..8)

    // ---- zero A panels (covers pads + initial h = 0) --------------------
    for (int i = tid; i < 2 * 16384 / 16; i += NTHR)
        ((uint4*)(smem + OFF_A0))[i] = make_uint4(0, 0, 0, 0);

    // ---- B fill (single fp16), tile-pair gate packing -------------------
    // unit j, gate g (0=i,1=f,2=g,3=o) -> B row
    //   n = (j>>4)*64 + ((j>>2)&3)*16 + (g>>1)*8 + (j&3)*2 + (g&1)
    // k: 0..27 = Wih, 28 = bias, 29..31 = 0, 32..95 = Whh.
    for (int idx = tid; idx < 256 * 96; idx += NTHR) {
        int orow = idx / 96, k = idx % 96;   // orow = g*64 + j (torch order)
        int g = orow >> 6, j = orow & 63;
        float w = 0.0f;
        if (k < IDIM)       w = Wih[orow * IDIM + k];
        else if (k == IDIM) w = bih[orow] + bhh[orow];
        else if (k >= 32)   w = Whh[orow * HDIM + (k - 32)];
        int n = ((j >> 4) << 6) + (((j >> 2) & 3) << 4) + ((g >> 1) << 3)
              + ((j & 3) << 1) + (g & 1);
        int p  = k >> 6, kl = k & 63;
        uint32_t sw = SWZ((uint32_t)(n * 128 + kl * 2));
        *(uint16_t*)(smem + (p ? OFF_B1 : OFF_B0) + sw) =
            __half_as_ushort(__float2half_rn(w));
    }
    // zero unused cols of B panel1 (kl 32..63)
    for (int idx = tid; idx < 256 * 32; idx += NTHR) {
        int n = idx >> 5, kl = 32 + (idx & 31);
        uint32_t sw = SWZ((uint32_t)(n * 128 + kl * 2));
        *(uint16_t*)(smem + OFF_B1 + sw) = 0;
    }
    // A col 28 = 1.0 for all rows (bias multiplier)
    if (tid < BT) {
        uint32_t sw = SWZ((uint32_t)(tid * 128 + IDIM * 2));
        *(uint16_t*)(smem + OFF_A0 + sw) = (uint16_t)0x3C00;
    }

    // ---- quad-local x mapping (t-invariant) + prefetch x_0 --------------
    const float* __restrict__ xb = x + (size_t)blockIdx.x * BT * TSTEPS * IDIM;
    int xoff[4], xsw[4];
#pragma unroll
    for (int i = 0; i < 4; i++) {
        int idx = ptid + i * 128;          // 0..511; valid < 448
        int brow = idx / IDIM, k = idx % IDIM;
        if (idx < 448) {
            xoff[i] = (mw * 16 + brow) * (TSTEPS * IDIM) + k;
            xsw[i]  = (int)SWZ((uint32_t)((mw * 16 + brow) * 128 + k * 2));
        } else { xoff[i] = -1; xsw[i] = 0; }
    }
    float xr[4];
#pragma unroll
    for (int i = 0; i < 4; i++) xr[i] = (xoff[i] >= 0) ? xb[xoff[i]] : 0.0f;

    // ---- per-thread GEMM/epilogue constants -----------------------------
    const int arow   = mw * 16 + (lane & 15);
    const int achunk = (lane >> 4) * 16;
    const int brow_l = ((lane >> 4) << 3) + (lane & 7);
    const int bchunk = ((lane >> 3) & 1) * 16;
    const int q      = lane & 3;                 // unit-within-pair
    const int r0     = mw * 16 + (lane >> 2);    // first owned batch row
    const int pan    = nq >> 1;                  // h panel for this quarter
    const uint32_t apan_h = sb + (pan ? OFF_A1 : OFF_A0);

    float cs[8];
#pragma unroll
    for (int m = 0; m < 8; m++) cs[m] = 0.0f;

    float* hst = (float*)(smem + OFF_HST);       // classifier staging

    __syncthreads();      // B, A-init visible

    for (int t = 0; t < TSTEPS; ++t) {
        // ---- write x_t into A panel0 cols 0..27 (quad rows only) --------
#pragma unroll
        for (int i = 0; i < 4; i++) {
            if (xoff[i] >= 0) {
                *(uint16_t*)(smem + OFF_A0 + xsw[i]) =
                    __half_as_ushort(__float2half_rn(xr[i]));
            }
        }
        QUAD_BAR(barid);     // quad's x_t + h_t writes visible to quad

        // ---- GEMM: 6 k16 steps x 4 tile-pairs ---------------------------
        float d[8][4];
#pragma unroll
        for (int m = 0; m < 8; m++) {
            d[m][0] = 0.0f; d[m][1] = 0.0f; d[m][2] = 0.0f; d[m][3] = 0.0f;
        }
#pragma unroll
        for (int ks = 0; ks < 6; ks++) {
            const int p  = (ks < 4) ? 0 : 1;
            const int cb = (ks < 4) ? ks * 32 : (ks - 4) * 32;
            const uint32_t aswz = SWZ((uint32_t)(arow * 128 + cb + achunk));
            uint32_t av[4];
            LDSM4(av[0], av[1], av[2], av[3],
                  sb + (p ? OFF_A1 : OFF_A0) + aswz);
#pragma unroll
            for (int g2 = 0; g2 < 4; g2++) {
                const int nb = nq * 64 + g2 * 16;
                const uint32_t bswz =
                    SWZ((uint32_t)((nb + brow_l) * 128 + cb + bchunk));
                uint32_t bv[4];
                LDSM4(bv[0], bv[1], bv[2], bv[3],
                      sb + (p ? OFF_B1 : OFF_B0) + bswz);
                MMA16816(d[2 * g2],     av, bv[0], bv[1]);
                MMA16816(d[2 * g2 + 1], av, bv[2], bv[3]);
            }
        }
        QUAD_BAR(barid);     // quad's A reads done before h/x overwrite

        // ---- prefetch x_{t+1} (overlaps epilogue) -----------------------
        if (t < TSTEPS - 1) {
#pragma unroll
            for (int i = 0; i < 4; i++)
                if (xoff[i] >= 0) xr[i] = xb[xoff[i] + (t + 1) * IDIM];
        }

        // ---- epilogue: tile pair tp -> unit j, rows r0, r0+8; no shfl ---
#pragma unroll
        for (int tp = 0; tp < 4; tp++) {
            const int j = 16 * nq + 4 * tp + q;
            const int bytecol = pan ? (2 * j - 64) : (64 + 2 * j);
#pragma unroll
            for (int rr = 0; rr < 2; rr++) {
                float gi = d[2 * tp][2 * rr + 0];
                float gf = d[2 * tp][2 * rr + 1];
                float gg = d[2 * tp + 1][2 * rr + 0];
                float go = d[2 * tp + 1][2 * rr + 1];
                float iv = sigap(gi), fv = sigap(gf);
                float gv = tanhap(gg), ov = sigap(go);
                const int m = tp * 2 + rr;
                float c = fv * cs[m] + iv * gv;
                cs[m] = c;
                float h = ov * tanhap(c);
                const int b = r0 + 8 * rr;
                const uint32_t sw = SWZ((uint32_t)(b * 128 + bytecol));
                *(uint16_t*)((char*)smem + (apan_h - sb) + sw) =
                    __half_as_ushort(__float2half_rn(h));
                if (t == TSTEPS - 1) hst[b * 65 + j] = h;
            }
        }
    }
    __syncthreads();         // all quads finished; hst complete

    // ---- classifier: out[b,cls] = b_cls + sum_j h[b,j]*Wcls[cls,j] ------
    const int bbase = blockIdx.x * BT;
    for (int idx = tid; idx < BT * 10; idx += NTHR) {
        int b = idx / 10, cls = idx % 10;
        float s = bcls[cls];
        const float* __restrict__ wc = Wcls + cls * HDIM;
#pragma unroll
        for (int j = 0; j < HDIM; j++) s += hst[b * 65 + j] * __ldg(&wc[j]);
        out[(size_t)(bbase + b) * 10 + cls] = s;
    }
}

extern "C" void kernel_launch(void* const* d_in, const int* in_sizes, int n_in,
                              void* d_out, int out_size) {
    const float* x    = (const float*)d_in[0];
    const float* Wih  = (const float*)d_in[1];
    const float* Whh  = (const float*)d_in[2];
    const float* bih  = (const float*)d_in[3];
    const float* bhh  = (const float*)d_in[4];
    const float* Wcls = (const float*)d_in[5];
    const float* bcls = (const float*)d_in[6];
    float* out = (float*)d_out;

    cudaFuncSetAttribute(lstm_mma_kernel,
                         cudaFuncAttributeMaxDynamicSharedMemorySize, SMEM_SZ);
    lstm_mma_kernel<<<16384 / BT, NTHR, SMEM_SZ>>>(x, Wih, Whh, bih, bhh,
                                                   Wcls, bcls, out);
}